// round 4
// baseline (speedup 1.0000x reference)
#include <cuda_runtime.h>
#include <math.h>

#define Bz 32
#define Lz 4096
#define Dz 1024
#define WARPS 8
#define NCTA 296                 // 148 SMs x occupancy 2 -> exactly one wave
#define GPB (Lz / 8)             // 512 eight-row groups per batch
#define GROUPS (Bz * GPB)        // 16384 groups total

// Scratch: up to 2 partials per CTA (range crosses <=1 batch boundary). 2.4 MB.
__device__ float g_m[NCTA * 2];
__device__ float g_s[NCTA * 2];
__device__ float g_acc[NCTA * 2][Dz];

// ---------------------------------------------------------------------------
// Pass 1: persistent single-wave. CTA c owns contiguous groups [g0, g1) over
// the flat (batch, row-group) space; splits at the (single) batch boundary
// into <=2 segments, runs warp-level online softmax with register
// accumulators across the whole segment, CTA-merges once per segment.
// ---------------------------------------------------------------------------
__global__ void __launch_bounds__(256, 2)
tap_pass1(const float* __restrict__ seq,
          const int* __restrict__ mask,        // bool marshalled as int32
          const float* __restrict__ query)
{
    const int c    = blockIdx.x;
    const int warp = threadIdx.x >> 5;
    const int lane = threadIdx.x & 31;
    const int t    = threadIdx.x;

    __shared__ float sm_m[WARPS];
    __shared__ float sm_s[WARPS];
    __shared__ float sm_acc[WARPS][Dz];        // 32 KB

    // Query slice in registers: d = ch*128 + lane*4 .. +3
    float4 q[8];
#pragma unroll
    for (int ch = 0; ch < 8; ch++)
        q[ch] = reinterpret_cast<const float4*>(query)[ch * 32 + lane];

    const int g0  = (int)((long long)c       * GROUPS / NCTA);
    const int g1  = (int)((long long)(c + 1) * GROUPS / NCTA);
    const int bb  = (g0 / GPB + 1) * GPB;      // first batch boundary after g0
    const int mid = (g1 < bb) ? g1 : bb;

    for (int seg = 0; seg < 2; seg++) {
        const int s0 = (seg == 0) ? g0  : mid;
        const int s1 = (seg == 0) ? mid : g1;
        const int p  = c * 2 + seg;

        if (s1 <= s0) {                        // empty 2nd segment (uniform)
            if (t == 0) { g_m[p] = -3.0e38f; g_s[p] = 0.0f; }
            break;
        }

        const int b = s0 / GPB;
        const int* mk = mask + (size_t)b * Lz;
        const float* sb = seq + (size_t)b * Lz * Dz;

        float m = -3.0e38f;
        float s = 0.0f;
        float4 acc[8];
#pragma unroll
        for (int ch = 0; ch < 8; ch++) acc[ch] = make_float4(0.f, 0.f, 0.f, 0.f);

        for (int g = s0 + warp; g < s1; g += WARPS) {
            const int row0 = (g - b * GPB) * 8;

            // 8-row group bitmap via ballot (one coalesced 32B mask read)
            const int mv = (lane < 8) ? mk[row0 + lane] : 0;
            unsigned bits = __ballot_sync(0xffffffffu, mv != 0) & 0xFFu;

            while (bits) {
                const int i = __ffs(bits) - 1;
                bits &= bits - 1;
                const float4* rp =
                    reinterpret_cast<const float4*>(sb + (size_t)(row0 + i) * Dz);

                float4 r[8];
                float dot = 0.f;
#pragma unroll
                for (int ch = 0; ch < 8; ch++) {
                    r[ch] = rp[ch * 32 + lane];
                    dot += r[ch].x * q[ch].x + r[ch].y * q[ch].y
                         + r[ch].z * q[ch].z + r[ch].w * q[ch].w;
                }
#pragma unroll
                for (int o = 16; o > 0; o >>= 1)
                    dot += __shfl_xor_sync(0xffffffffu, dot, o);
                dot *= 0.03125f;               // 1/sqrt(1024)

                const float mnew = fmaxf(m, dot);
                const float corr = __expf(m - mnew);
                const float w    = __expf(dot - mnew);
                s = s * corr + w;
#pragma unroll
                for (int ch = 0; ch < 8; ch++) {
                    acc[ch].x = acc[ch].x * corr + w * r[ch].x;
                    acc[ch].y = acc[ch].y * corr + w * r[ch].y;
                    acc[ch].z = acc[ch].z * corr + w * r[ch].z;
                    acc[ch].w = acc[ch].w * corr + w * r[ch].w;
                }
                m = mnew;
            }
        }

        // ---- CTA merge: 8 warp states -> 1 partial ----
        if (lane == 0) { sm_m[warp] = m; sm_s[warp] = s; }
        float4* wp = reinterpret_cast<float4*>(sm_acc[warp]);
#pragma unroll
        for (int ch = 0; ch < 8; ch++) wp[ch * 32 + lane] = acc[ch];
        __syncthreads();

        float M = -3.0e38f;
#pragma unroll
        for (int w = 0; w < WARPS; w++) M = fmaxf(M, sm_m[w]);
        float e[WARPS];
        float S = 0.f;
#pragma unroll
        for (int w = 0; w < WARPS; w++) {
            e[w] = __expf(sm_m[w] - M);
            S += e[w] * sm_s[w];
        }

        float4 o4 = make_float4(0.f, 0.f, 0.f, 0.f);
#pragma unroll
        for (int w = 0; w < WARPS; w++) {
            const float4 a = reinterpret_cast<const float4*>(sm_acc[w])[t];
            o4.x += e[w] * a.x; o4.y += e[w] * a.y;
            o4.z += e[w] * a.z; o4.w += e[w] * a.w;
        }
        reinterpret_cast<float4*>(g_acc[p])[t] = o4;
        if (t == 0) { g_m[p] = M; g_s[p] = S; }

        __syncthreads();                       // smem reuse for segment 1
    }
}

// ---------------------------------------------------------------------------
// Pass 2: per batch, merge the ~11 partials whose CTA ranges intersect it.
// Candidate CTAs are a small contiguous window (ranges are monotone in c).
// ---------------------------------------------------------------------------
__global__ void __launch_bounds__(256)
tap_pass2(float* __restrict__ out)
{
    const int b = blockIdx.x;
    const int t = threadIdx.x;

    const int c0 = max(0, (b * NCTA) / Bz - 1);
    const int c1 = min(NCTA - 1, ((b + 1) * NCTA) / Bz + 1);

    // Pass A: global max over matching partials
    float M = -3.0e38f;
    for (int c = c0; c <= c1; c++) {
        const int gg0 = (int)((long long)c       * GROUPS / NCTA);
        const int gg1 = (int)((long long)(c + 1) * GROUPS / NCTA);
        const int bb  = (gg0 / GPB + 1) * GPB;
        const int mid = (gg1 < bb) ? gg1 : bb;
        if (gg0 / GPB == b)                 M = fmaxf(M, g_m[c * 2]);
        if (gg1 > mid && (mid / GPB) == b)  M = fmaxf(M, g_m[c * 2 + 1]);
    }

    // Pass B: normalizer + weighted accumulator merge
    float S = 0.f;
    float4 o4 = make_float4(0.f, 0.f, 0.f, 0.f);
    for (int c = c0; c <= c1; c++) {
        const int gg0 = (int)((long long)c       * GROUPS / NCTA);
        const int gg1 = (int)((long long)(c + 1) * GROUPS / NCTA);
        const int bb  = (gg0 / GPB + 1) * GPB;
        const int mid = (gg1 < bb) ? gg1 : bb;
#pragma unroll
        for (int seg = 0; seg < 2; seg++) {
            const bool match = (seg == 0) ? (gg0 / GPB == b)
                                          : (gg1 > mid && (mid / GPB) == b);
            if (!match) continue;
            const int p = c * 2 + seg;
            const float sv = g_s[p];
            const float e  = __expf(g_m[p] - M);
            S += e * sv;
            if (sv > 0.f) {
                const float4 a = reinterpret_cast<const float4*>(g_acc[p])[t];
                o4.x += e * a.x; o4.y += e * a.y;
                o4.z += e * a.z; o4.w += e * a.w;
            }
        }
    }
    const float invS = 1.0f / S;
    o4.x *= invS; o4.y *= invS; o4.z *= invS; o4.w *= invS;
    reinterpret_cast<float4*>(out)[b * (Dz / 4) + t] = o4;
}

// ---------------------------------------------------------------------------
extern "C" void kernel_launch(void* const* d_in, const int* in_sizes, int n_in,
                              void* d_out, int out_size)
{
    const float* seq   = (const float*)d_in[0];
    const int*   mask  = (const int*)d_in[1];
    const float* query = (const float*)d_in[2];
    float*       out   = (float*)d_out;

    tap_pass1<<<NCTA, 256>>>(seq, mask, query);
    tap_pass2<<<Bz, 256>>>(out);
}